// round 12
// baseline (speedup 1.0000x reference)
#include <cuda_runtime.h>
#include <cuda_fp16.h>
#include <cstdint>

#define BN 4
#define SQ 2048
#define DM 1024
#define MT (BN * SQ)
#define BK 64
#define NTHR 512
#define ASTR 72            // halves per A-tile row (128B data + 16B pad)
#define BSTR 136           // halves per trans-B-tile row (256B data + 16B pad)
#define ABYTES (128 * ASTR * 2)          // 18432
#define BBYTES 18432
#define STAGE (ABYTES + BBYTES)          // 36864
#define NSTG 3
#define SMEM_DYN (NSTG * STAGE + 512)

// Scratch (__device__ globals; no allocation allowed)
__device__ __half g_x[(size_t)MT * DM];
__device__ __half g_w[(size_t)3 * DM * DM];
__device__ __half g_q[(size_t)MT * DM];
__device__ __half g_k[(size_t)MT * DM];
__device__ __half g_v[(size_t)MT * DM];
__device__ __half g_sc[(size_t)BN * SQ * SQ];   // unnormalized exp weights
__device__ float  g_lp[(size_t)MT * 64];        // row-sum partials

// ---------------------------------------------------------------------------
__device__ __forceinline__ uint32_t smem_u32(const void* p) {
    uint32_t a;
    asm("{ .reg .u64 t; cvta.to.shared.u64 t, %1; cvt.u32.u64 %0, t; }" : "=r"(a) : "l"(p));
    return a;
}

#define CP16(sa, g) \
    asm volatile("cp.async.cg.shared.global [%0], [%1], 16;" :: "r"(sa), "l"(g))
#define CP_COMMIT() asm volatile("cp.async.commit_group;" ::: "memory")
#define CP_WAITG1() asm volatile("cp.async.wait_group 1;" ::: "memory")

#define LDSM4(r0, r1, r2, r3, addr) \
    asm volatile("ldmatrix.sync.aligned.m8n8.x4.shared.b16 {%0,%1,%2,%3}, [%4];" \
        : "=r"(r0), "=r"(r1), "=r"(r2), "=r"(r3) : "r"(addr))
#define LDSM4T(r0, r1, r2, r3, addr) \
    asm volatile("ldmatrix.sync.aligned.m8n8.x4.trans.shared.b16 {%0,%1,%2,%3}, [%4];" \
        : "=r"(r0), "=r"(r1), "=r"(r2), "=r"(r3) : "r"(addr))

__device__ __forceinline__ void mma_f16(float& c0, float& c1, float& c2, float& c3,
                                        uint32_t a0, uint32_t a1, uint32_t a2, uint32_t a3,
                                        uint32_t b0, uint32_t b1) {
    asm volatile(
        "mma.sync.aligned.m16n8k16.row.col.f32.f16.f16.f32 "
        "{%0,%1,%2,%3}, {%4,%5,%6,%7}, {%8,%9}, {%0,%1,%2,%3};"
        : "+f"(c0), "+f"(c1), "+f"(c2), "+f"(c3)
        : "r"(a0), "r"(a1), "r"(a2), "r"(a3), "r"(b0), "r"(b1));
}

// ---------------------------------------------------------------------------
// GEMM body. MODE: 0 = projection; 3 = scores (exp epilogue + partials);
// 4 = PV (fused row-sum prologue, normalize, write out).
// CTA tile 128x128, BK=64, 512 threads; warp grid 4x4, warp tile 32x32
// (32 acc regs/thread -> 2 CTAs/SM -> 32 warps/SM for latency hiding).
// 3-stage cp.async pipeline, one __syncthreads per k-iter.
// ---------------------------------------------------------------------------
template <int MODE>
__device__ __forceinline__ void mm_body(int bx, int by, int bz, int which,
                                        float* __restrict__ Out, char* dsm)
{
    constexpr bool BTRANS = (MODE != 3);

    const __half* Ab;
    const __half* Bb;
    size_t lda, ldb;
    int nt;
    if (MODE == 0) {
        Ab = g_x + (size_t)by * 128 * DM;                         lda = DM;
        Bb = g_w + (size_t)which * DM * DM + bx * 128;            ldb = DM;  // [k][n]
        nt = DM / BK;
    } else if (MODE == 3) {
        Ab = g_q + ((size_t)bz * SQ + by * 128) * DM;             lda = DM;
        Bb = g_k + ((size_t)bz * SQ + bx * 128) * DM;             ldb = DM;  // [n][k]
        nt = DM / BK;
    } else {
        Ab = g_sc + ((size_t)bz * SQ + by * 128) * SQ;            lda = SQ;
        Bb = g_v + ((size_t)bz * SQ) * DM + bx * 128;             ldb = DM;  // [k][n]
        nt = (by + 1) * 2;
    }

    const uint32_t sbase = smem_u32(dsm);
    float* s_l = reinterpret_cast<float*>(dsm + NSTG * STAGE);  // 128 row sums (PV)
    const int tid = threadIdx.x;
    const int lane = tid & 31, wid = tid >> 5;
    const int wm = wid >> 2, wn = wid & 3;        // 4x4 warp grid

    float acc[2][4][4];
#pragma unroll
    for (int i = 0; i < 2; ++i)
#pragma unroll
        for (int j = 0; j < 4; ++j)
#pragma unroll
            for (int r = 0; r < 4; ++r) acc[i][j][r] = 0.f;

    auto stageA = [&](int kt, int buf) {
        const uint32_t abase = sbase + buf * STAGE;
#pragma unroll
        for (int u = 0; u < 2; ++u) {
            const int idx = tid + u * NTHR;         // 1024 16B chunks
            const int row = idx >> 3, c8 = idx & 7;
            CP16(abase + (uint32_t)(row * ASTR + c8 * 8) * 2,
                 Ab + (size_t)row * lda + kt * BK + c8 * 8);
        }
    };
    auto stageB = [&](int kt, int buf) {
        const uint32_t bbase = sbase + buf * STAGE + ABYTES;
        if (BTRANS) {
#pragma unroll
            for (int u = 0; u < 2; ++u) {
                const int idx = tid + u * NTHR;     // 64 rows x 16 chunks
                const int row = idx >> 4, c8 = idx & 15;
                CP16(bbase + (uint32_t)(row * BSTR + c8 * 8) * 2,
                     Bb + (size_t)(kt * BK + row) * ldb + c8 * 8);
            }
        } else {
#pragma unroll
            for (int u = 0; u < 2; ++u) {
                const int idx = tid + u * NTHR;     // 128 rows x 8 chunks
                const int row = idx >> 3, c8 = idx & 7;
                CP16(bbase + (uint32_t)(row * ASTR + c8 * 8) * 2,
                     Bb + (size_t)row * ldb + kt * BK + c8 * 8);
            }
        }
    };

    stageA(0, 0); stageB(0, 0);
    CP_COMMIT();
    if (1 < nt) { stageA(1, 1); stageB(1, 1); }
    CP_COMMIT();

    // PV: fused row-sum reduce, overlapped with the in-flight cp.async stages.
    // Identical serial accumulation order to the old reduce kernel.
    if (MODE == 4) {
        if (tid < 128) {
            const int row = bz * SQ + by * 128 + tid;
            const int nvalid4 = (by + 1);
            const float4* p = reinterpret_cast<const float4*>(g_lp + (size_t)row * 64);
            float s = 0.f;
            for (int j = 0; j < nvalid4; ++j) {
                float4 v = p[j];
                s += v.x; s += v.y; s += v.z; s += v.w;
            }
            s_l[tid] = s;
        }
        // visibility via the __syncthreads at top of first k-iter
    }

    const int a_row = wm * 32 + (lane & 15);
    const int a_col8 = (lane >> 4) << 3;
    const int bt_row = lane & 15;
    const int bt_col = wn * 32 + ((lane >> 4) << 3);
    const int g4 = lane >> 3;
    const int bn_row = wn * 32 + ((g4 >> 1) << 3) + (lane & 7);
    const int bn_col8 = (g4 & 1) << 3;

    for (int kt = 0; kt < nt; ++kt) {
        CP_WAITG1();
        __syncthreads();

        if (kt + 2 < nt) { stageA(kt + 2, (kt + 2) % NSTG); stageB(kt + 2, (kt + 2) % NSTG); }
        CP_COMMIT();

        const uint32_t Abase = sbase + (kt % NSTG) * STAGE;
        const uint32_t Bbase = Abase + ABYTES;

#pragma unroll
        for (int ks = 0; ks < 4; ++ks) {
            uint32_t af[2][4];
#pragma unroll
            for (int ma = 0; ma < 2; ++ma) {
                const uint32_t ad = Abase +
                    (uint32_t)((a_row + ma * 16) * ASTR + ks * 16 + a_col8) * 2;
                LDSM4(af[ma][0], af[ma][1], af[ma][2], af[ma][3], ad);
            }
            uint32_t bf[4][2];
#pragma unroll
            for (int np = 0; np < 2; ++np) {
                uint32_t r0, r1, r2, r3;
                if (BTRANS) {
                    const uint32_t bd = Bbase +
                        (uint32_t)((ks * 16 + bt_row) * BSTR + bt_col + np * 16) * 2;
                    LDSM4T(r0, r1, r2, r3, bd);
                } else {
                    const uint32_t bd = Bbase +
                        (uint32_t)((bn_row + np * 16) * ASTR + ks * 16 + bn_col8) * 2;
                    LDSM4(r0, r1, r2, r3, bd);
                }
                bf[np * 2 + 0][0] = r0; bf[np * 2 + 0][1] = r1;
                bf[np * 2 + 1][0] = r2; bf[np * 2 + 1][1] = r3;
            }
#pragma unroll
            for (int ma = 0; ma < 2; ++ma)
#pragma unroll
                for (int na = 0; na < 4; ++na)
                    mma_f16(acc[ma][na][0], acc[ma][na][1], acc[ma][na][2], acc[ma][na][3],
                            af[ma][0], af[ma][1], af[ma][2], af[ma][3],
                            bf[na][0], bf[na][1]);
        }
    }

    // ---- epilogue --------------------------------------------------------
    if (MODE == 3) {
        const float scale = 0.03125f;  // 1/sqrt(1024)
        __half* C = g_sc + (size_t)bz * SQ * SQ;
#pragma unroll
        for (int ma = 0; ma < 2; ++ma) {
            const int rl0 = by * 128 + wm * 32 + ma * 16 + (lane >> 2);
            const int rl1 = rl0 + 8;
            float part0 = 0.f, part1 = 0.f;
#pragma unroll
            for (int na = 0; na < 4; ++na) {
                const int c0 = bx * 128 + wn * 32 + na * 8 + (lane & 3) * 2;
                float p00 = __expf(acc[ma][na][0] * scale - 8.f);
                float p01 = __expf(acc[ma][na][1] * scale - 8.f);
                float p10 = __expf(acc[ma][na][2] * scale - 8.f);
                float p11 = __expf(acc[ma][na][3] * scale - 8.f);
                if (bx == by) {
                    if (c0     > rl0) p00 = 0.f;
                    if (c0 + 1 > rl0) p01 = 0.f;
                    if (c0     > rl1) p10 = 0.f;
                    if (c0 + 1 > rl1) p11 = 0.f;
                }
                __half h00 = __float2half_rn(p00), h01 = __float2half_rn(p01);
                __half h10 = __float2half_rn(p10), h11 = __float2half_rn(p11);
                part0 += __half2float(h00) + __half2float(h01);
                part1 += __half2float(h10) + __half2float(h11);
                *reinterpret_cast<__half2*>(C + (size_t)rl0 * SQ + c0) =
                    __halves2half2(h00, h01);
                *reinterpret_cast<__half2*>(C + (size_t)rl1 * SQ + c0) =
                    __halves2half2(h10, h11);
            }
            part0 += __shfl_xor_sync(0xffffffffu, part0, 1);
            part0 += __shfl_xor_sync(0xffffffffu, part0, 2);
            part1 += __shfl_xor_sync(0xffffffffu, part1, 1);
            part1 += __shfl_xor_sync(0xffffffffu, part1, 2);
            if ((lane & 3) == 0) {
                const int idx = bx * 4 + wn;
                g_lp[(size_t)(bz * SQ + rl0) * 64 + idx] = part0;
                g_lp[(size_t)(bz * SQ + rl1) * 64 + idx] = part1;
            }
        }
        return;
    }

#pragma unroll
    for (int ma = 0; ma < 2; ++ma) {
        const int lr0 = wm * 32 + ma * 16 + (lane >> 2);
        const int r0 = by * 128 + lr0;
        float inv0 = 1.f, inv1 = 1.f;
        if (MODE == 4) {
            inv0 = __fdividef(1.f, s_l[lr0]);
            inv1 = __fdividef(1.f, s_l[lr0 + 8]);
        }
#pragma unroll
        for (int na = 0; na < 4; ++na) {
            const int c0 = bx * 128 + wn * 32 + na * 8 + (lane & 3) * 2;
            float v0 = acc[ma][na][0], v1 = acc[ma][na][1];
            float v2 = acc[ma][na][2], v3 = acc[ma][na][3];

            if (MODE == 0) {
                __half* C = (which == 0) ? g_q : (which == 1) ? g_k : g_v;
                *reinterpret_cast<__half2*>(C + (size_t)r0 * DM + c0) =
                    __halves2half2(__float2half_rn(v0), __float2half_rn(v1));
                *reinterpret_cast<__half2*>(C + (size_t)(r0 + 8) * DM + c0) =
                    __halves2half2(__float2half_rn(v2), __float2half_rn(v3));
            } else {
                float* C = Out + (size_t)bz * SQ * DM;
                *reinterpret_cast<float2*>(C + (size_t)r0 * DM + c0) =
                    make_float2(v0 * inv0, v1 * inv0);
                *reinterpret_cast<float2*>(C + (size_t)(r0 + 8) * DM + c0) =
                    make_float2(v2 * inv1, v3 * inv1);
            }
        }
    }
}

// ---------------------------------------------------------------------------
// Kernel wrappers
// ---------------------------------------------------------------------------
__global__ __launch_bounds__(NTHR, 2) void k_proj_qk()
{
    extern __shared__ char dsm[];
    mm_body<0>((int)blockIdx.x & 7, (int)blockIdx.y, 0, (int)blockIdx.x >> 3,
               nullptr, dsm);
}

// Fused scores + V projection, grid (16, 16, 6)
__global__ __launch_bounds__(NTHR, 2) void k_scores_projv()
{
    extern __shared__ char dsm[];
    const int bx = blockIdx.x, by = blockIdx.y, bz = blockIdx.z;
    if (bz < 4) {
        if (bx > by) return;
        mm_body<3>(bx, by, bz, 0, nullptr, dsm);
    } else {
        const int id = (bz - 4) * 256 + by * 16 + bx;   // 0..511
        mm_body<0>(id & 7, id >> 3, 0, 2, nullptr, dsm);
    }
}

// PV with fused row-sum; heavy i-tiles first.
__global__ __launch_bounds__(NTHR, 2) void k_pv(float* __restrict__ Out)
{
    extern __shared__ char dsm[];
    mm_body<4>((int)blockIdx.x, (int)gridDim.y - 1 - (int)blockIdx.y,
               (int)blockIdx.z, 0, Out, dsm);
}

// ---------------------------------------------------------------------------
// fp32 -> fp16 conversion, 16 elems/thread, 4 independent loads in flight.
// ---------------------------------------------------------------------------
__global__ __launch_bounds__(256) void roundh_all(
    const float4* __restrict__ x, const float4* __restrict__ Wq,
    const float4* __restrict__ Wk, const float4* __restrict__ Wv)
{
    const int bid = blockIdx.x;
    const float4* src;
    uint4* dst;
    int li;
    if (bid < 2048) {
        src = x;   dst = (uint4*)g_x;                         li = bid;
    } else if (bid < 2304) {
        src = Wq;  dst = (uint4*)g_w;                         li = bid - 2048;
    } else if (bid < 2560) {
        src = Wk;  dst = (uint4*)(g_w + (size_t)DM * DM);     li = bid - 2304;
    } else {
        src = Wv;  dst = (uint4*)(g_w + (size_t)2 * DM * DM); li = bid - 2560;
    }
    const int i = li * 256 + threadIdx.x;
    float4 a0 = src[4 * i + 0];
    float4 a1 = src[4 * i + 1];
    float4 a2 = src[4 * i + 2];
    float4 a3 = src[4 * i + 3];
    __half2 h0 = __floats2half2_rn(a0.x, a0.y);
    __half2 h1 = __floats2half2_rn(a0.z, a0.w);
    __half2 h2 = __floats2half2_rn(a1.x, a1.y);
    __half2 h3 = __floats2half2_rn(a1.z, a1.w);
    __half2 h4 = __floats2half2_rn(a2.x, a2.y);
    __half2 h5 = __floats2half2_rn(a2.z, a2.w);
    __half2 h6 = __floats2half2_rn(a3.x, a3.y);
    __half2 h7 = __floats2half2_rn(a3.z, a3.w);
    uint4 o0, o1;
    o0.x = *reinterpret_cast<uint32_t*>(&h0);
    o0.y = *reinterpret_cast<uint32_t*>(&h1);
    o0.z = *reinterpret_cast<uint32_t*>(&h2);
    o0.w = *reinterpret_cast<uint32_t*>(&h3);
    o1.x = *reinterpret_cast<uint32_t*>(&h4);
    o1.y = *reinterpret_cast<uint32_t*>(&h5);
    o1.z = *reinterpret_cast<uint32_t*>(&h6);
    o1.w = *reinterpret_cast<uint32_t*>(&h7);
    dst[2 * i + 0] = o0;
    dst[2 * i + 1] = o1;
}

// ---------------------------------------------------------------------------
extern "C" void kernel_launch(void* const* d_in, const int* in_sizes, int n_in,
                              void* d_out, int out_size)
{
    const float* x  = (const float*)d_in[0];
    const float* Wq = (const float*)d_in[1];
    const float* Wk = (const float*)d_in[2];
    const float* Wv = (const float*)d_in[3];
    float* out = (float*)d_out;

    (void)cudaFuncSetAttribute(k_proj_qk,
        cudaFuncAttributeMaxDynamicSharedMemorySize, SMEM_DYN);
    (void)cudaFuncSetAttribute(k_scores_projv,
        cudaFuncAttributeMaxDynamicSharedMemorySize, SMEM_DYN);
    (void)cudaFuncSetAttribute(k_pv,
        cudaFuncAttributeMaxDynamicSharedMemorySize, SMEM_DYN);

    dim3 blk(NTHR);

    roundh_all<<<2816, 256>>>((const float4*)x, (const float4*)Wq,
                              (const float4*)Wk, (const float4*)Wv);

    dim3 gQK(16, 64);
    k_proj_qk<<<gQK, blk, SMEM_DYN>>>();

    dim3 gSV(16, 16, 6);
    k_scores_projv<<<gSV, blk, SMEM_DYN>>>();

    dim3 gPV(8, 16, 4);
    k_pv<<<gPV, blk, SMEM_DYN>>>(out);
}

// round 13
// speedup vs baseline: 1.1406x; 1.1406x over previous
#include <cuda_runtime.h>
#include <cuda_fp16.h>
#include <cstdint>

#define BN 4
#define SQ 2048
#define DM 1024
#define MT (BN * SQ)
#define BK 64
#define NTHR 256
#define ASTR 72            // halves per A-tile row (128B data + 16B pad)
#define BSTR 136           // halves per trans-B-tile row (256B data + 16B pad)
#define ABYTES (128 * ASTR * 2)          // 18432
#define BBYTES 18432
#define STAGE (ABYTES + BBYTES)          // 36864
#define NSTG 5
#define SMEM_DYN (NSTG * STAGE + 512)    // 184832

// Scratch (__device__ globals; no allocation allowed)
__device__ __half g_x[(size_t)MT * DM];
__device__ __half g_w[(size_t)3 * DM * DM];
__device__ __half g_q[(size_t)MT * DM];
__device__ __half g_k[(size_t)MT * DM];
__device__ __half g_v[(size_t)MT * DM];
__device__ __half g_sc[(size_t)BN * SQ * SQ];   // unnormalized exp weights
__device__ float  g_lp[(size_t)MT * 64];        // row-sum partials

// ---------------------------------------------------------------------------
__device__ __forceinline__ uint32_t smem_u32(const void* p) {
    uint32_t a;
    asm("{ .reg .u64 t; cvta.to.shared.u64 t, %1; cvt.u32.u64 %0, t; }" : "=r"(a) : "l"(p));
    return a;
}

#define CP16(sa, g) \
    asm volatile("cp.async.cg.shared.global [%0], [%1], 16;" :: "r"(sa), "l"(g))
#define CP_COMMIT() asm volatile("cp.async.commit_group;" ::: "memory")
#define CP_WAIT2()  asm volatile("cp.async.wait_group 2;" ::: "memory")
#define CP_WAIT3()  asm volatile("cp.async.wait_group 3;" ::: "memory")

#define LDSM4(r0, r1, r2, r3, addr) \
    asm volatile("ldmatrix.sync.aligned.m8n8.x4.shared.b16 {%0,%1,%2,%3}, [%4];" \
        : "=r"(r0), "=r"(r1), "=r"(r2), "=r"(r3) : "r"(addr))
#define LDSM4T(r0, r1, r2, r3, addr) \
    asm volatile("ldmatrix.sync.aligned.m8n8.x4.trans.shared.b16 {%0,%1,%2,%3}, [%4];" \
        : "=r"(r0), "=r"(r1), "=r"(r2), "=r"(r3) : "r"(addr))

__device__ __forceinline__ void mma_f16(float& c0, float& c1, float& c2, float& c3,
                                        uint32_t a0, uint32_t a1, uint32_t a2, uint32_t a3,
                                        uint32_t b0, uint32_t b1) {
    asm volatile(
        "mma.sync.aligned.m16n8k16.row.col.f32.f16.f16.f32 "
        "{%0,%1,%2,%3}, {%4,%5,%6,%7}, {%8,%9}, {%0,%1,%2,%3};"
        : "+f"(c0), "+f"(c1), "+f"(c2), "+f"(c3)
        : "r"(a0), "r"(a1), "r"(a2), "r"(a3), "r"(b0), "r"(b1));
}

// ---------------------------------------------------------------------------
// GEMM body. MODE: 0 = projection; 3 = scores (exp epilogue + partials);
// 4 = PV (fused row-sum prologue, normalize, write out).
// CTA tile 128x128, BK=64, 256 threads; warp grid 2x4, warp tile 64x32.
// 5-stage cp.async pipeline + double-buffered ldmatrix fragments
// (CUTLASS-style: low occupancy, deep register pipelining).
// ---------------------------------------------------------------------------
template <int MODE>
__device__ __forceinline__ void mm_body(int bx, int by, int bz, int which,
                                        float* __restrict__ Out, char* dsm)
{
    constexpr bool BTRANS = (MODE != 3);

    const __half* Ab;
    const __half* Bb;
    size_t lda, ldb;
    int nt;
    if (MODE == 0) {
        Ab = g_x + (size_t)by * 128 * DM;                         lda = DM;
        Bb = g_w + (size_t)which * DM * DM + bx * 128;            ldb = DM;  // [k][n]
        nt = DM / BK;
    } else if (MODE == 3) {
        Ab = g_q + ((size_t)bz * SQ + by * 128) * DM;             lda = DM;
        Bb = g_k + ((size_t)bz * SQ + bx * 128) * DM;             ldb = DM;  // [n][k]
        nt = DM / BK;
    } else {
        Ab = g_sc + ((size_t)bz * SQ + by * 128) * SQ;            lda = SQ;
        Bb = g_v + ((size_t)bz * SQ) * DM + bx * 128;             ldb = DM;  // [k][n]
        nt = (by + 1) * 2;
    }

    const uint32_t sbase = smem_u32(dsm);
    float* s_l = reinterpret_cast<float*>(dsm + NSTG * STAGE);  // 128 row sums (PV)
    const int tid = threadIdx.x;
    const int lane = tid & 31, wid = tid >> 5;
    const int wm = wid >> 2, wn = wid & 3;        // 2x4 warp grid, 64x32 tile

    float acc[4][4][4];
#pragma unroll
    for (int i = 0; i < 4; ++i)
#pragma unroll
        for (int j = 0; j < 4; ++j)
#pragma unroll
            for (int r = 0; r < 4; ++r) acc[i][j][r] = 0.f;

    auto stageA = [&](int kt, int buf) {
        const uint32_t abase = sbase + buf * STAGE;
#pragma unroll
        for (int u = 0; u < 4; ++u) {
            const int idx = tid + u * NTHR;         // 1024 16B chunks
            const int row = idx >> 3, c8 = idx & 7;
            CP16(abase + (uint32_t)(row * ASTR + c8 * 8) * 2,
                 Ab + (size_t)row * lda + kt * BK + c8 * 8);
        }
    };
    auto stageB = [&](int kt, int buf) {
        const uint32_t bbase = sbase + buf * STAGE + ABYTES;
        if (BTRANS) {
#pragma unroll
            for (int u = 0; u < 4; ++u) {
                const int idx = tid + u * NTHR;     // 64 rows x 16 chunks
                const int row = idx >> 4, c8 = idx & 15;
                CP16(bbase + (uint32_t)(row * BSTR + c8 * 8) * 2,
                     Bb + (size_t)(kt * BK + row) * ldb + c8 * 8);
            }
        } else {
#pragma unroll
            for (int u = 0; u < 4; ++u) {
                const int idx = tid + u * NTHR;     // 128 rows x 8 chunks
                const int row = idx >> 3, c8 = idx & 7;
                CP16(bbase + (uint32_t)(row * ASTR + c8 * 8) * 2,
                     Bb + (size_t)row * ldb + kt * BK + c8 * 8);
            }
        }
    };

    // Prologue: stages 0..3 committed as 4 groups (empty commits OK).
#pragma unroll
    for (int s = 0; s < NSTG - 1; ++s) {
        if (s < nt) { stageA(s, s); stageB(s, s); }
        CP_COMMIT();
    }

    // PV: fused row-sum reduce, overlapped with in-flight cp.async stages.
    // Identical serial accumulation order to the old reduce kernel.
    if (MODE == 4) {
        if (tid < 128) {
            const int row = bz * SQ + by * 128 + tid;
            const int nvalid4 = (by + 1);
            const float4* p = reinterpret_cast<const float4*>(g_lp + (size_t)row * 64);
            float s = 0.f;
            for (int j = 0; j < nvalid4; ++j) {
                float4 v = p[j];
                s += v.x; s += v.y; s += v.z; s += v.w;
            }
            s_l[tid] = s;
        }
    }

    const int a_row = wm * 64 + (lane & 15);
    const int a_col8 = (lane >> 4) << 3;
    const int bt_row = lane & 15;
    const int bt_col = wn * 32 + ((lane >> 4) << 3);
    const int g4 = lane >> 3;
    const int bn_row = wn * 32 + ((g4 >> 1) << 3) + (lane & 7);
    const int bn_col8 = (g4 & 1) << 3;

    // Double-buffered fragments
    uint32_t af[2][4][4];
    uint32_t bf[2][4][2];

    auto load_frags = [&](int fb, int kt_, int ks_) {
        const uint32_t Abase = sbase + (kt_ % NSTG) * STAGE;
        const uint32_t Bbase = Abase + ABYTES;
#pragma unroll
        for (int ma = 0; ma < 4; ++ma) {
            const uint32_t ad = Abase +
                (uint32_t)((a_row + ma * 16) * ASTR + ks_ * 16 + a_col8) * 2;
            LDSM4(af[fb][ma][0], af[fb][ma][1], af[fb][ma][2], af[fb][ma][3], ad);
        }
#pragma unroll
        for (int np = 0; np < 2; ++np) {
            uint32_t r0, r1, r2, r3;
            if (BTRANS) {
                const uint32_t bd = Bbase +
                    (uint32_t)((ks_ * 16 + bt_row) * BSTR + bt_col + np * 16) * 2;
                LDSM4T(r0, r1, r2, r3, bd);
            } else {
                const uint32_t bd = Bbase +
                    (uint32_t)((bn_row + np * 16) * ASTR + ks_ * 16 + bn_col8) * 2;
                LDSM4(r0, r1, r2, r3, bd);
            }
            bf[fb][np * 2 + 0][0] = r0; bf[fb][np * 2 + 0][1] = r1;
            bf[fb][np * 2 + 1][0] = r2; bf[fb][np * 2 + 1][1] = r3;
        }
    };

    // Wait for stage 0 (first of 4 groups), then preload ks=0 fragments.
    CP_WAIT3();
    __syncthreads();
    load_frags(0, 0, 0);

    for (int kt = 0; kt < nt; ++kt) {
#pragma unroll
        for (int ks = 0; ks < 4; ++ks) {
            const int cb = ks & 1;           // compute buffer
            const int nb = cb ^ 1;           // load buffer
            if (ks == 3) {
                // Make stage kt+1 visible; recycle buffer (kt+4)%NSTG.
                CP_WAIT2();
                __syncthreads();
                if (kt + NSTG - 1 < nt) {
                    stageA(kt + NSTG - 1, (kt + NSTG - 1) % NSTG);
                    stageB(kt + NSTG - 1, (kt + NSTG - 1) % NSTG);
                }
                CP_COMMIT();
                const int nkt = (kt + 1 < nt) ? kt + 1 : kt;
                load_frags(nb, nkt, 0);
            } else {
                load_frags(nb, kt, ks + 1);
            }
#pragma unroll
            for (int ma = 0; ma < 4; ++ma)
#pragma unroll
                for (int na = 0; na < 4; ++na)
                    mma_f16(acc[ma][na][0], acc[ma][na][1], acc[ma][na][2], acc[ma][na][3],
                            af[cb][ma][0], af[cb][ma][1], af[cb][ma][2], af[cb][ma][3],
                            bf[cb][na][0], bf[cb][na][1]);
        }
    }

    // ---- epilogue --------------------------------------------------------
    if (MODE == 3) {
        const float scale = 0.03125f;  // 1/sqrt(1024)
        __half* C = g_sc + (size_t)bz * SQ * SQ;
#pragma unroll
        for (int ma = 0; ma < 4; ++ma) {
            const int rl0 = by * 128 + wm * 64 + ma * 16 + (lane >> 2);
            const int rl1 = rl0 + 8;
            float part0 = 0.f, part1 = 0.f;
#pragma unroll
            for (int na = 0; na < 4; ++na) {
                const int c0 = bx * 128 + wn * 32 + na * 8 + (lane & 3) * 2;
                float p00 = __expf(acc[ma][na][0] * scale - 8.f);
                float p01 = __expf(acc[ma][na][1] * scale - 8.f);
                float p10 = __expf(acc[ma][na][2] * scale - 8.f);
                float p11 = __expf(acc[ma][na][3] * scale - 8.f);
                if (bx == by) {
                    if (c0     > rl0) p00 = 0.f;
                    if (c0 + 1 > rl0) p01 = 0.f;
                    if (c0     > rl1) p10 = 0.f;
                    if (c0 + 1 > rl1) p11 = 0.f;
                }
                __half h00 = __float2half_rn(p00), h01 = __float2half_rn(p01);
                __half h10 = __float2half_rn(p10), h11 = __float2half_rn(p11);
                part0 += __half2float(h00) + __half2float(h01);
                part1 += __half2float(h10) + __half2float(h11);
                *reinterpret_cast<__half2*>(C + (size_t)rl0 * SQ + c0) =
                    __halves2half2(h00, h01);
                *reinterpret_cast<__half2*>(C + (size_t)rl1 * SQ + c0) =
                    __halves2half2(h10, h11);
            }
            part0 += __shfl_xor_sync(0xffffffffu, part0, 1);
            part0 += __shfl_xor_sync(0xffffffffu, part0, 2);
            part1 += __shfl_xor_sync(0xffffffffu, part1, 1);
            part1 += __shfl_xor_sync(0xffffffffu, part1, 2);
            if ((lane & 3) == 0) {
                const int idx = bx * 4 + wn;
                g_lp[(size_t)(bz * SQ + rl0) * 64 + idx] = part0;
                g_lp[(size_t)(bz * SQ + rl1) * 64 + idx] = part1;
            }
        }
        return;
    }

#pragma unroll
    for (int ma = 0; ma < 4; ++ma) {
        const int lr0 = wm * 64 + ma * 16 + (lane >> 2);
        const int r0 = by * 128 + lr0;
        float inv0 = 1.f, inv1 = 1.f;
        if (MODE == 4) {
            inv0 = __fdividef(1.f, s_l[lr0]);
            inv1 = __fdividef(1.f, s_l[lr0 + 8]);
        }
#pragma unroll
        for (int na = 0; na < 4; ++na) {
            const int c0 = bx * 128 + wn * 32 + na * 8 + (lane & 3) * 2;
            float v0 = acc[ma][na][0], v1 = acc[ma][na][1];
            float v2 = acc[ma][na][2], v3 = acc[ma][na][3];

            if (MODE == 0) {
                __half* C = (which == 0) ? g_q : (which == 1) ? g_k : g_v;
                *reinterpret_cast<__half2*>(C + (size_t)r0 * DM + c0) =
                    __halves2half2(__float2half_rn(v0), __float2half_rn(v1));
                *reinterpret_cast<__half2*>(C + (size_t)(r0 + 8) * DM + c0) =
                    __halves2half2(__float2half_rn(v2), __float2half_rn(v3));
            } else {
                float* C = Out + (size_t)bz * SQ * DM;
                *reinterpret_cast<float2*>(C + (size_t)r0 * DM + c0) =
                    make_float2(v0 * inv0, v1 * inv0);
                *reinterpret_cast<float2*>(C + (size_t)(r0 + 8) * DM + c0) =
                    make_float2(v2 * inv1, v3 * inv1);
            }
        }
    }
}

// ---------------------------------------------------------------------------
// Kernel wrappers (occ 1: registers spent on fragment double-buffering)
// ---------------------------------------------------------------------------
__global__ __launch_bounds__(NTHR, 1) void k_proj_qk()
{
    extern __shared__ char dsm[];
    mm_body<0>((int)blockIdx.x & 7, (int)blockIdx.y, 0, (int)blockIdx.x >> 3,
               nullptr, dsm);
}

// Fused scores + V projection, grid (16, 16, 6)
__global__ __launch_bounds__(NTHR, 1) void k_scores_projv()
{
    extern __shared__ char dsm[];
    const int bx = blockIdx.x, by = blockIdx.y, bz = blockIdx.z;
    if (bz < 4) {
        if (bx > by) return;
        mm_body<3>(bx, by, bz, 0, nullptr, dsm);
    } else {
        const int id = (bz - 4) * 256 + by * 16 + bx;   // 0..511
        mm_body<0>(id & 7, id >> 3, 0, 2, nullptr, dsm);
    }
}

// PV with fused row-sum; heavy i-tiles first.
__global__ __launch_bounds__(NTHR, 1) void k_pv(float* __restrict__ Out)
{
    extern __shared__ char dsm[];
    mm_body<4>((int)blockIdx.x, (int)gridDim.y - 1 - (int)blockIdx.y,
               (int)blockIdx.z, 0, Out, dsm);
}

// ---------------------------------------------------------------------------
// fp32 -> fp16 conversion, 16 elems/thread, 4 independent loads in flight.
// ---------------------------------------------------------------------------
__global__ __launch_bounds__(256) void roundh_all(
    const float4* __restrict__ x, const float4* __restrict__ Wq,
    const float4* __restrict__ Wk, const float4* __restrict__ Wv)
{
    const int bid = blockIdx.x;
    const float4* src;
    uint4* dst;
    int li;
    if (bid < 2048) {
        src = x;   dst = (uint4*)g_x;                         li = bid;
    } else if (bid < 2304) {
        src = Wq;  dst = (uint4*)g_w;                         li = bid - 2048;
    } else if (bid < 2560) {
        src = Wk;  dst = (uint4*)(g_w + (size_t)DM * DM);     li = bid - 2304;
    } else {
        src = Wv;  dst = (uint4*)(g_w + (size_t)2 * DM * DM); li = bid - 2560;
    }
    const int i = li * 256 + threadIdx.x;
    float4 a0 = src[4 * i + 0];
    float4 a1 = src[4 * i + 1];
    float4 a2 = src[4 * i + 2];
    float4 a3 = src[4 * i + 3];
    __half2 h0 = __floats2half2_rn(a0.x, a0.y);
    __half2 h1 = __floats2half2_rn(a0.z, a0.w);
    __half2 h2 = __floats2half2_rn(a1.x, a1.y);
    __half2 h3 = __floats2half2_rn(a1.z, a1.w);
    __half2 h4 = __floats2half2_rn(a2.x, a2.y);
    __half2 h5 = __floats2half2_rn(a2.z, a2.w);
    __half2 h6 = __floats2half2_rn(a3.x, a3.y);
    __half2 h7 = __floats2half2_rn(a3.z, a3.w);
    uint4 o0, o1;
    o0.x = *reinterpret_cast<uint32_t*>(&h0);
    o0.y = *reinterpret_cast<uint32_t*>(&h1);
    o0.z = *reinterpret_cast<uint32_t*>(&h2);
    o0.w = *reinterpret_cast<uint32_t*>(&h3);
    o1.x = *reinterpret_cast<uint32_t*>(&h4);
    o1.y = *reinterpret_cast<uint32_t*>(&h5);
    o1.z = *reinterpret_cast<uint32_t*>(&h6);
    o1.w = *reinterpret_cast<uint32_t*>(&h7);
    dst[2 * i + 0] = o0;
    dst[2 * i + 1] = o1;
}

// ---------------------------------------------------------------------------
extern "C" void kernel_launch(void* const* d_in, const int* in_sizes, int n_in,
                              void* d_out, int out_size)
{
    const float* x  = (const float*)d_in[0];
    const float* Wq = (const float*)d_in[1];
    const float* Wk = (const float*)d_in[2];
    const float* Wv = (const float*)d_in[3];
    float* out = (float*)d_out;

    (void)cudaFuncSetAttribute(k_proj_qk,
        cudaFuncAttributeMaxDynamicSharedMemorySize, SMEM_DYN);
    (void)cudaFuncSetAttribute(k_scores_projv,
        cudaFuncAttributeMaxDynamicSharedMemorySize, SMEM_DYN);
    (void)cudaFuncSetAttribute(k_pv,
        cudaFuncAttributeMaxDynamicSharedMemorySize, SMEM_DYN);

    dim3 blk(NTHR);

    roundh_all<<<2816, 256>>>((const float4*)x, (const float4*)Wq,
                              (const float4*)Wk, (const float4*)Wv);

    dim3 gQK(16, 64);
    k_proj_qk<<<gQK, blk, SMEM_DYN>>>();

    dim3 gSV(16, 16, 6);
    k_scores_projv<<<gSV, blk, SMEM_DYN>>>();

    dim3 gPV(8, 16, 4);
    k_pv<<<gPV, blk, SMEM_DYN>>>(out);
}